// round 13
// baseline (speedup 1.0000x reference)
#include <cuda_runtime.h>

#define NN 100000
#define EE 1600000
#define GG 64

// ---------------- scratch (no runtime allocation allowed) ----------------
__device__ float g_inv[NN];
__device__ int   g_cnt[NN];
__device__ float g_agg[(size_t)NN * 128];
__device__ float g_x1[(size_t)NN * 128];
__device__ float g_x2[(size_t)NN * 128];
__device__ float g_pool[GG * 256];

// ---------------- zero-fill helpers ----------------
__global__ void zero_cnt_kernel() {
    int i = blockIdx.x * blockDim.x + threadIdx.x;
    if (i < NN) g_cnt[i] = 0;
}

__global__ void zero_agg_kernel(int n) {   // zeros first n floats of g_agg
    int i = blockIdx.x * blockDim.x + threadIdx.x;
    if (i < n) g_agg[i] = 0.f;
}

__global__ void zero_pool_kernel() {
    int i = blockIdx.x * blockDim.x + threadIdx.x;
    if (i < GG * 256) g_pool[i] = 0.f;
}

// ---------------- degree count + inverse ----------------
// NOTE: edge_index / batch are INT32 (JAX x64 disabled -> int64 request
// silently becomes int32). Reading them as 64-bit was the round-2..12 bug.
__global__ void count_kernel(const int* __restrict__ dst, int e) {
    int i = blockIdx.x * blockDim.x + threadIdx.x;
    if (i < e) atomicAdd(&g_cnt[dst[i]], 1);
}

__global__ void inv_kernel(int n) {
    int i = blockIdx.x * blockDim.x + threadIdx.x;
    if (i < n) g_inv[i] = 1.0f / (float)max(g_cnt[i], 1);
}

// ---------------- layer 0: scatter 7-dim features ----------------
__global__ void scatter7_kernel(const float* __restrict__ x,
                                const int* __restrict__ src,
                                const int* __restrict__ dst, int e) {
    int i = blockIdx.x * blockDim.x + threadIdx.x;
    if (i >= e) return;
    int s = src[i], d = dst[i];
    const float* xs = x + (size_t)s * 7;
    float* ag = g_agg + (size_t)d * 7;
#pragma unroll
    for (int k = 0; k < 7; k++) atomicAdd(&ag[k], xs[k]);
}

// ---------------- layer 0 fused: x@Wl + bl + mean@Wr -> BN -> ReLU -> g_x1 ----
__global__ void __launch_bounds__(128) layer0_kernel(
    const float* __restrict__ x,
    const float* __restrict__ Wl, const float* __restrict__ bl,
    const float* __restrict__ Wr,
    const float* __restrict__ gma, const float* __restrict__ bet,
    const float* __restrict__ rm, const float* __restrict__ rv, int n)
{
    int j = threadIdx.x;  // 0..127 output column
    float wl[7], wr[7];
#pragma unroll
    for (int k = 0; k < 7; k++) { wl[k] = Wl[k * 128 + j]; wr[k] = Wr[k * 128 + j]; }
    float sc = gma[j] * rsqrtf(rv[j] + 1e-5f);
    float of = bet[j] + (bl[j] - rm[j]) * sc;

    int i0 = blockIdx.x * 64;
    int iend = min(i0 + 64, n);
    for (int i = i0; i < iend; i++) {
        float iv = g_inv[i];
        const float* xr = x + (size_t)i * 7;
        const float* ar = g_agg + (size_t)i * 7;
        float acc = 0.f;
#pragma unroll
        for (int k = 0; k < 7; k++) acc += xr[k] * wl[k] + (ar[k] * iv) * wr[k];
        g_x1[(size_t)i * 128 + j] = fmaxf(acc * sc + of, 0.f);
    }
}

// ---------------- 128-dim scatter: warp per edge; SRC selects g_x1/g_x2 ------
template <int SRC>
__global__ void __launch_bounds__(256) scatter128_kernel(
    const int* __restrict__ src,
    const int* __restrict__ dst, int e)
{
    const float* x;
    if constexpr (SRC == 1) x = g_x1; else x = g_x2;
    int w = (blockIdx.x * blockDim.x + threadIdx.x) >> 5;
    int lane = threadIdx.x & 31;
    if (w >= e) return;
    int s = src[w], d = dst[w];
    const float* xs = x + (size_t)s * 128;
    float* ag = g_agg + (size_t)d * 128;
#pragma unroll
    for (int k = 0; k < 4; k++) {
        int idx = lane + k * 32;
        atomicAdd(&ag[idx], xs[idx]);
    }
}

// ---------------- agg *= inv (compute mean in place) -------------------------
__global__ void normalize_kernel(int n) {
    int i = blockIdx.x * blockDim.x + threadIdx.x;  // over n*128 floats
    if (i >= n * 128) return;
    int node = i >> 7;
    g_agg[i] *= g_inv[node];
}

// ---------------- fused GEMM: [x | mean] @ [Wl ; Wr] + bl -> BN -> ReLU ------
// SRC: 1 -> g_x1, 2 -> g_x2.  DSTSEL: 1 -> g_x2, 0 -> out param.
template <int DOUT, int SRC, int DSTSEL>
__global__ void __launch_bounds__(256) sage_gemm_bn_relu(
    const float* __restrict__ Wl, const float* __restrict__ Wr,
    const float* __restrict__ bl,
    const float* __restrict__ gma, const float* __restrict__ bet,
    const float* __restrict__ rm, const float* __restrict__ rv,
    float* __restrict__ out, int n)
{
    const float* x;
    if constexpr (SRC == 1) x = g_x1; else x = g_x2;

    constexpr int BM = 128, BN = 64, BK = 16;
    constexpr int ASTRIDE = BM + 4;
    __shared__ float As[BK][ASTRIDE];
    __shared__ float Bs[BK][BN];

    int t = threadIdx.x;
    int tx = t & 15;          // 0..15 -> 4 cols each
    int ty = t >> 4;          // 0..15 -> 8 rows each
    int m0 = blockIdx.x * BM;
    int n0 = blockIdx.y * BN;

    float acc[8][4];
#pragma unroll
    for (int r = 0; r < 8; r++)
#pragma unroll
        for (int c = 0; c < 4; c++) acc[r][c] = 0.f;

    int a_k4 = (t & 3) * 4;   // k offset within tile (0,4,8,12)
    int a_row = t >> 2;       // 0..63 (plus +64 on second pass)
    int b_j4 = (t & 15) * 4;  // col offset
    int b_kk = t >> 4;        // 0..15

#pragma unroll 1
    for (int kt = 0; kt < 256 / BK; ++kt) {
        int k0 = kt * BK;
        const float* Asrc = (k0 < 128) ? x : (const float*)g_agg;
        int klocal = (k0 < 128) ? k0 : (k0 - 128);

        // load A tile (transposed into As[k][m])
#pragma unroll
        for (int h = 0; h < 2; ++h) {
            int row = a_row + h * 64;
            int grow = m0 + row;
            float4 v = make_float4(0.f, 0.f, 0.f, 0.f);
            if (grow < n)
                v = *(const float4*)(Asrc + (size_t)grow * 128 + klocal + a_k4);
            As[a_k4 + 0][row] = v.x;
            As[a_k4 + 1][row] = v.y;
            As[a_k4 + 2][row] = v.z;
            As[a_k4 + 3][row] = v.w;
        }
        // load B tile
        {
            const float* W = (k0 < 128) ? Wl : Wr;
            float4 v = *(const float4*)(W + (size_t)(klocal + b_kk) * DOUT + n0 + b_j4);
            *(float4*)&Bs[b_kk][b_j4] = v;
        }
        __syncthreads();

#pragma unroll
        for (int kk = 0; kk < BK; ++kk) {
            float a[8], b[4];
            *(float4*)&a[0] = *(const float4*)&As[kk][ty * 8];
            *(float4*)&a[4] = *(const float4*)&As[kk][ty * 8 + 4];
            *(float4*)&b[0] = *(const float4*)&Bs[kk][tx * 4];
#pragma unroll
            for (int r = 0; r < 8; r++)
#pragma unroll
                for (int c = 0; c < 4; c++) acc[r][c] += a[r] * b[c];
        }
        __syncthreads();
    }

    // epilogue: folded BN + ReLU
    float s[4], o[4];
#pragma unroll
    for (int c = 0; c < 4; c++) {
        int j = n0 + tx * 4 + c;
        float sc = gma[j] * rsqrtf(rv[j] + 1e-5f);
        s[c] = sc;
        o[c] = bet[j] + (bl[j] - rm[j]) * sc;
    }

    float* dstp;
    if constexpr (DSTSEL == 1) dstp = g_x2; else dstp = out;

#pragma unroll
    for (int r = 0; r < 8; r++) {
        int grow = m0 + ty * 8 + r;
        if (grow < n) {
#pragma unroll
            for (int c = 0; c < 4; c++) {
                float v = fmaxf(acc[r][c] * s[c] + o[c], 0.f);
                dstp[(size_t)grow * DOUT + n0 + tx * 4 + c] = v;
            }
        }
    }
}

// ---------------- global add pool (batch is sorted) into g_pool --------------
__global__ void __launch_bounds__(256) pool_kernel(
    const int* __restrict__ batch,
    const float* __restrict__ x3,  // [n,256]
    int n)
{
    int col = threadIdx.x;  // 256 cols
    int i0 = blockIdx.x * 64;
    if (i0 >= n) return;
    int iend = min(i0 + 64, n);
    int cur = batch[i0];
    float acc = 0.f;
    for (int i = i0; i < iend; i++) {
        int b = batch[i];
        if (b != cur) {
            atomicAdd(&g_pool[(size_t)cur * 256 + col], acc);
            acc = 0.f;
            cur = b;
        }
        acc += x3[(size_t)i * 256 + col];
    }
    atomicAdd(&g_pool[(size_t)cur * 256 + col], acc);
}

// ---------------- copy pooled result to d_out --------------------------------
__global__ void copy_pool_kernel(float* __restrict__ out) {
    int i = blockIdx.x * blockDim.x + threadIdx.x;
    if (i < GG * 256) out[i] = g_pool[i];
}

// ---------------- launch: kernel launches ONLY -------------------------------
extern "C" void kernel_launch(void* const* d_in, const int* in_sizes, int n_in,
                              void* d_out, int out_size)
{
    const float* x     = (const float*)d_in[0];
    const int*   ei    = (const int*)d_in[1];    // int32 (JAX default x64-off)
    const int*   batch = (const int*)d_in[2];    // int32

    const float *Wl0=(const float*)d_in[3],  *bl0=(const float*)d_in[4],  *Wr0=(const float*)d_in[5];
    const float *g0 =(const float*)d_in[6],  *be0=(const float*)d_in[7],  *rm0=(const float*)d_in[8],  *rv0=(const float*)d_in[9];
    const float *Wl1=(const float*)d_in[10], *bl1=(const float*)d_in[11], *Wr1=(const float*)d_in[12];
    const float *g1 =(const float*)d_in[13], *be1=(const float*)d_in[14], *rm1=(const float*)d_in[15], *rv1=(const float*)d_in[16];
    const float *Wl2=(const float*)d_in[17], *bl2=(const float*)d_in[18], *Wr2=(const float*)d_in[19];
    const float *g2 =(const float*)d_in[20], *be2=(const float*)d_in[21], *rm2=(const float*)d_in[22], *rv2=(const float*)d_in[23];

    const int* src = ei;
    const int* dst = ei + EE;

    float* out_pooled = (float*)d_out;
    float* out_x      = (float*)d_out + (size_t)GG * 256;

    // degree counts
    zero_cnt_kernel<<<(NN + 255) / 256, 256>>>();
    count_kernel<<<(EE + 255) / 256, 256>>>(dst, EE);
    inv_kernel<<<(NN + 255) / 256, 256>>>(NN);

    // ---- layer 0 (din=7 -> dout=128) ----
    zero_agg_kernel<<<(NN * 7 + 255) / 256, 256>>>(NN * 7);
    scatter7_kernel<<<(EE + 255) / 256, 256>>>(x, src, dst, EE);
    layer0_kernel<<<(NN + 63) / 64, 128>>>(x, Wl0, bl0, Wr0, g0, be0, rm0, rv0, NN);

    // ---- layer 1 (128 -> 128) ----
    zero_agg_kernel<<<(NN * 128 + 255) / 256, 256>>>(NN * 128);
    scatter128_kernel<1><<<EE / 8, 256>>>(src, dst, EE);
    normalize_kernel<<<(NN * 128 + 255) / 256, 256>>>(NN);
    sage_gemm_bn_relu<128, 1, 1><<<dim3((NN + 127) / 128, 2), 256>>>(
        Wl1, Wr1, bl1, g1, be1, rm1, rv1, out_x, NN);

    // ---- layer 2 (128 -> 256) ----
    zero_agg_kernel<<<(NN * 128 + 255) / 256, 256>>>(NN * 128);
    scatter128_kernel<2><<<EE / 8, 256>>>(src, dst, EE);
    normalize_kernel<<<(NN * 128 + 255) / 256, 256>>>(NN);
    sage_gemm_bn_relu<256, 2, 0><<<dim3((NN + 127) / 128, 4), 256>>>(
        Wl2, Wr2, bl2, g2, be2, rm2, rv2, out_x, NN);

    // ---- global add pool ----
    zero_pool_kernel<<<(GG * 256 + 255) / 256, 256>>>();
    pool_kernel<<<(NN + 63) / 64, 256>>>(batch, out_x, NN);
    copy_pool_kernel<<<(GG * 256 + 255) / 256, 256>>>(out_pooled);
}

// round 14
// speedup vs baseline: 1.0829x; 1.0829x over previous
#include <cuda_runtime.h>

#define NN 100000
#define EE 1600000
#define GG 64

typedef unsigned long long u64;

// ---------------- packed f32x2 helpers (FFMA2 — ptxas never emits this) ------
__device__ __forceinline__ u64 pack2(float lo, float hi) {
    u64 r; asm("mov.b64 %0, {%1, %2};" : "=l"(r) : "f"(lo), "f"(hi)); return r;
}
__device__ __forceinline__ void ffma2(u64& d, u64 a, u64 b) {
    asm("fma.rn.f32x2 %0, %1, %2, %3;" : "=l"(d) : "l"(a), "l"(b), "l"(d));
}
__device__ __forceinline__ void unpack2(u64 v, float& lo, float& hi) {
    asm("mov.b64 {%0, %1}, %2;" : "=f"(lo), "=f"(hi) : "l"(v));
}

// ---------------- scratch (no runtime allocation allowed) ----------------
__device__ float g_inv[NN];
__device__ int   g_cnt[NN];
__device__ float g_agg[(size_t)NN * 128];   // raw neighbor sums (inv folded into GEMM)
__device__ float g_x1[(size_t)NN * 128];
__device__ float g_x2[(size_t)NN * 128];
__device__ float g_pool[GG * 256];

// ---------------- zero-fill helpers ----------------
__global__ void zero_cnt_kernel() {
    int i = blockIdx.x * blockDim.x + threadIdx.x;
    if (i < NN) g_cnt[i] = 0;
}

__global__ void zero_agg_kernel(int n) {
    int i = blockIdx.x * blockDim.x + threadIdx.x;
    if (i < n) g_agg[i] = 0.f;
}

__global__ void zero_pool_kernel() {
    int i = blockIdx.x * blockDim.x + threadIdx.x;
    if (i < GG * 256) g_pool[i] = 0.f;
}

// ---------------- degree count + inverse (indices are INT32) -----------------
__global__ void count_kernel(const int* __restrict__ dst, int e) {
    int i = blockIdx.x * blockDim.x + threadIdx.x;
    if (i < e) atomicAdd(&g_cnt[dst[i]], 1);
}

__global__ void inv_kernel(int n) {
    int i = blockIdx.x * blockDim.x + threadIdx.x;
    if (i < n) g_inv[i] = 1.0f / (float)max(g_cnt[i], 1);
}

// ---------------- layer 0: scatter 7-dim features ----------------
__global__ void scatter7_kernel(const float* __restrict__ x,
                                const int* __restrict__ src,
                                const int* __restrict__ dst, int e) {
    int i = blockIdx.x * blockDim.x + threadIdx.x;
    if (i >= e) return;
    int s = src[i], d = dst[i];
    const float* xs = x + (size_t)s * 7;
    float* ag = g_agg + (size_t)d * 7;
#pragma unroll
    for (int k = 0; k < 7; k++) atomicAdd(&ag[k], xs[k]);
}

// ---------------- layer 0 fused: x@Wl + bl + mean@Wr -> BN -> ReLU -> g_x1 ----
__global__ void __launch_bounds__(128) layer0_kernel(
    const float* __restrict__ x,
    const float* __restrict__ Wl, const float* __restrict__ bl,
    const float* __restrict__ Wr,
    const float* __restrict__ gma, const float* __restrict__ bet,
    const float* __restrict__ rm, const float* __restrict__ rv, int n)
{
    int j = threadIdx.x;  // 0..127 output column
    float wl[7], wr[7];
#pragma unroll
    for (int k = 0; k < 7; k++) { wl[k] = Wl[k * 128 + j]; wr[k] = Wr[k * 128 + j]; }
    float sc = gma[j] * rsqrtf(rv[j] + 1e-5f);
    float of = bet[j] + (bl[j] - rm[j]) * sc;

    int i0 = blockIdx.x * 64;
    int iend = min(i0 + 64, n);
    for (int i = i0; i < iend; i++) {
        float iv = g_inv[i];
        const float* xr = x + (size_t)i * 7;
        const float* ar = g_agg + (size_t)i * 7;
        float acc = 0.f;
#pragma unroll
        for (int k = 0; k < 7; k++) acc += xr[k] * wl[k] + (ar[k] * iv) * wr[k];
        g_x1[(size_t)i * 128 + j] = fmaxf(acc * sc + of, 0.f);
    }
}

// ---------------- 128-dim scatter: warp per edge; SRC selects g_x1/g_x2 ------
template <int SRC>
__global__ void __launch_bounds__(256) scatter128_kernel(
    const int* __restrict__ src,
    const int* __restrict__ dst, int e)
{
    const float* x;
    if constexpr (SRC == 1) x = g_x1; else x = g_x2;
    int w = (blockIdx.x * blockDim.x + threadIdx.x) >> 5;
    int lane = threadIdx.x & 31;
    if (w >= e) return;
    int s = src[w], d = dst[w];
    const float* xs = x + (size_t)s * 128;
    float* ag = g_agg + (size_t)d * 128;
#pragma unroll
    for (int k = 0; k < 4; k++) {
        int idx = lane + k * 32;
        atomicAdd(&ag[idx], xs[idx]);
    }
}

// ---------------- fused GEMM: [x | agg*inv] @ [Wl ; Wr] + bl -> BN -> ReLU ---
// Packed-f32x2 FFMA2 inner loop (2x fp32 FMA throughput vs scalar FFMA).
// Normalize (mean = agg * g_inv) folded into the A-tile load for k >= 128.
// SRC: 1 -> g_x1, 2 -> g_x2.  DSTSEL: 1 -> g_x2, 0 -> out param.
template <int DOUT, int SRC, int DSTSEL>
__global__ void __launch_bounds__(256) sage_gemm_bn_relu(
    const float* __restrict__ Wl, const float* __restrict__ Wr,
    const float* __restrict__ bl,
    const float* __restrict__ gma, const float* __restrict__ bet,
    const float* __restrict__ rm, const float* __restrict__ rv,
    float* __restrict__ out, int n)
{
    const float* x;
    if constexpr (SRC == 1) x = g_x1; else x = g_x2;

    constexpr int BM = 128, BN = 64, BK = 16;
    constexpr int ASTRIDE = BM + 4;
    __shared__ float As[BK][ASTRIDE];
    __shared__ float Bs[BK][BN];

    int t = threadIdx.x;
    int tx = t & 15;          // 0..15 -> 4 cols each
    int ty = t >> 4;          // 0..15 -> 8 rows (4 row-pairs) each
    int m0 = blockIdx.x * BM;
    int n0 = blockIdx.y * BN;

    // accumulators: 4 row-pairs x 4 cols, packed f32x2 (rows r2*2, r2*2+1)
    u64 acc2[4][4];
#pragma unroll
    for (int r = 0; r < 4; r++)
#pragma unroll
        for (int c = 0; c < 4; c++) acc2[r][c] = 0ull;

    int a_k4 = (t & 3) * 4;   // k offset within tile (0,4,8,12)
    int a_row = t >> 2;       // 0..63 (plus +64 on second pass)
    int b_j4 = (t & 15) * 4;  // col offset
    int b_kk = t >> 4;        // 0..15

#pragma unroll 1
    for (int kt = 0; kt < 256 / BK; ++kt) {
        int k0 = kt * BK;
        const float* Asrc = (k0 < 128) ? x : (const float*)g_agg;
        int klocal = (k0 < 128) ? k0 : (k0 - 128);

        // load A tile (transposed into As[k][m]); fold inv for the mean half
#pragma unroll
        for (int h = 0; h < 2; ++h) {
            int row = a_row + h * 64;
            int grow = m0 + row;
            float4 v = make_float4(0.f, 0.f, 0.f, 0.f);
            if (grow < n) {
                v = *(const float4*)(Asrc + (size_t)grow * 128 + klocal + a_k4);
                if (k0 >= 128) {
                    float iv = g_inv[grow];
                    v.x *= iv; v.y *= iv; v.z *= iv; v.w *= iv;
                }
            }
            As[a_k4 + 0][row] = v.x;
            As[a_k4 + 1][row] = v.y;
            As[a_k4 + 2][row] = v.z;
            As[a_k4 + 3][row] = v.w;
        }
        // load B tile
        {
            const float* W = (k0 < 128) ? Wl : Wr;
            float4 v = *(const float4*)(W + (size_t)(klocal + b_kk) * DOUT + n0 + b_j4);
            *(float4*)&Bs[b_kk][b_j4] = v;
        }
        __syncthreads();

#pragma unroll
        for (int kk = 0; kk < BK; ++kk) {
            // A: 8 consecutive rows = 4 packed f32x2
            u64 a2[4];
            {
                const u64* ap = (const u64*)&As[kk][ty * 8];
                a2[0] = ap[0]; a2[1] = ap[1]; a2[2] = ap[2]; a2[3] = ap[3];
            }
            // B: 4 cols, each broadcast into both halves
            float b[4];
            *(float4*)&b[0] = *(const float4*)&Bs[kk][tx * 4];
            u64 bb[4];
#pragma unroll
            for (int c = 0; c < 4; c++) bb[c] = pack2(b[c], b[c]);
#pragma unroll
            for (int r = 0; r < 4; r++)
#pragma unroll
                for (int c = 0; c < 4; c++) ffma2(acc2[r][c], a2[r], bb[c]);
        }
        __syncthreads();
    }

    // epilogue: folded BN + ReLU
    float s[4], o[4];
#pragma unroll
    for (int c = 0; c < 4; c++) {
        int j = n0 + tx * 4 + c;
        float sc = gma[j] * rsqrtf(rv[j] + 1e-5f);
        s[c] = sc;
        o[c] = bet[j] + (bl[j] - rm[j]) * sc;
    }

    float* dstp;
    if constexpr (DSTSEL == 1) dstp = g_x2; else dstp = out;

#pragma unroll
    for (int r2 = 0; r2 < 4; r2++) {
#pragma unroll
        for (int half = 0; half < 2; half++) {
            int grow = m0 + ty * 8 + r2 * 2 + half;
            if (grow < n) {
#pragma unroll
                for (int c = 0; c < 4; c++) {
                    float lo, hi;
                    unpack2(acc2[r2][c], lo, hi);
                    float a = half ? hi : lo;
                    float v = fmaxf(a * s[c] + o[c], 0.f);
                    dstp[(size_t)grow * DOUT + n0 + tx * 4 + c] = v;
                }
            }
        }
    }
}

// ---------------- global add pool (batch is sorted) into g_pool --------------
__global__ void __launch_bounds__(256) pool_kernel(
    const int* __restrict__ batch,
    const float* __restrict__ x3,  // [n,256]
    int n)
{
    int col = threadIdx.x;  // 256 cols
    int i0 = blockIdx.x * 64;
    if (i0 >= n) return;
    int iend = min(i0 + 64, n);
    int cur = batch[i0];
    float acc = 0.f;
    for (int i = i0; i < iend; i++) {
        int b = batch[i];
        if (b != cur) {
            atomicAdd(&g_pool[(size_t)cur * 256 + col], acc);
            acc = 0.f;
            cur = b;
        }
        acc += x3[(size_t)i * 256 + col];
    }
    atomicAdd(&g_pool[(size_t)cur * 256 + col], acc);
}

// ---------------- copy pooled result to d_out --------------------------------
__global__ void copy_pool_kernel(float* __restrict__ out) {
    int i = blockIdx.x * blockDim.x + threadIdx.x;
    if (i < GG * 256) out[i] = g_pool[i];
}

// ---------------- launch: kernel launches ONLY -------------------------------
extern "C" void kernel_launch(void* const* d_in, const int* in_sizes, int n_in,
                              void* d_out, int out_size)
{
    const float* x     = (const float*)d_in[0];
    const int*   ei    = (const int*)d_in[1];    // int32
    const int*   batch = (const int*)d_in[2];    // int32

    const float *Wl0=(const float*)d_in[3],  *bl0=(const float*)d_in[4],  *Wr0=(const float*)d_in[5];
    const float *g0 =(const float*)d_in[6],  *be0=(const float*)d_in[7],  *rm0=(const float*)d_in[8],  *rv0=(const float*)d_in[9];
    const float *Wl1=(const float*)d_in[10], *bl1=(const float*)d_in[11], *Wr1=(const float*)d_in[12];
    const float *g1 =(const float*)d_in[13], *be1=(const float*)d_in[14], *rm1=(const float*)d_in[15], *rv1=(const float*)d_in[16];
    const float *Wl2=(const float*)d_in[17], *bl2=(const float*)d_in[18], *Wr2=(const float*)d_in[19];
    const float *g2 =(const float*)d_in[20], *be2=(const float*)d_in[21], *rm2=(const float*)d_in[22], *rv2=(const float*)d_in[23];

    const int* src = ei;
    const int* dst = ei + EE;

    float* out_pooled = (float*)d_out;
    float* out_x      = (float*)d_out + (size_t)GG * 256;

    // degree counts
    zero_cnt_kernel<<<(NN + 255) / 256, 256>>>();
    count_kernel<<<(EE + 255) / 256, 256>>>(dst, EE);
    inv_kernel<<<(NN + 255) / 256, 256>>>(NN);

    // ---- layer 0 (din=7 -> dout=128) ----
    zero_agg_kernel<<<(NN * 7 + 255) / 256, 256>>>(NN * 7);
    scatter7_kernel<<<(EE + 255) / 256, 256>>>(x, src, dst, EE);
    layer0_kernel<<<(NN + 63) / 64, 128>>>(x, Wl0, bl0, Wr0, g0, be0, rm0, rv0, NN);

    // ---- layer 1 (128 -> 128) ----
    zero_agg_kernel<<<(NN * 128 + 255) / 256, 256>>>(NN * 128);
    scatter128_kernel<1><<<EE / 8, 256>>>(src, dst, EE);
    sage_gemm_bn_relu<128, 1, 1><<<dim3((NN + 127) / 128, 2), 256>>>(
        Wl1, Wr1, bl1, g1, be1, rm1, rv1, out_x, NN);

    // ---- layer 2 (128 -> 256) ----
    zero_agg_kernel<<<(NN * 128 + 255) / 256, 256>>>(NN * 128);
    scatter128_kernel<2><<<EE / 8, 256>>>(src, dst, EE);
    sage_gemm_bn_relu<256, 2, 0><<<dim3((NN + 127) / 128, 4), 256>>>(
        Wl2, Wr2, bl2, g2, be2, rm2, rv2, out_x, NN);

    // ---- global add pool ----
    zero_pool_kernel<<<(GG * 256 + 255) / 256, 256>>>();
    pool_kernel<<<(NN + 63) / 64, 256>>>(batch, out_x, NN);
    copy_pool_kernel<<<(GG * 256 + 255) / 256, 256>>>(out_pooled);
}